// round 9
// baseline (speedup 1.0000x reference)
#include <cuda_runtime.h>
#include <cuda_fp16.h>
#include <cstdint>
#include <math.h>

// Problem constants
#define Bv   4
#define Cv   256
#define Hv   64
#define Wv   64
#define HW   4096          // Hv*Wv
#define NPIX 16384         // Bv*HW
#define NEL  4194304u      // Bv*Cv*HW
#define NHEAD 8
#define DHEAD 32
#define WELEM 65536        // 256*256 weight matrix elems
#define NWMAT 10

// Scratch: 8 fp32 tensors + 8 fp16 tensors + fp16 weights (~203 MB).
__device__ float g_scratch[12u * NEL + 400000u];

// ---------------------------------------------------------------------------
// PTX helpers
// ---------------------------------------------------------------------------
__device__ __forceinline__ void cp_async16(void* smem_dst, const void* gsrc) {
    uint32_t s = (uint32_t)__cvta_generic_to_shared(smem_dst);
    asm volatile("cp.async.ca.shared.global [%0], [%1], 16;\n" :: "r"(s), "l"(gsrc));
}
__device__ __forceinline__ void cp_commit() {
    asm volatile("cp.async.commit_group;\n");
}
template<int N> __device__ __forceinline__ void cp_wait() {
    asm volatile("cp.async.wait_group %0;\n" :: "n"(N));
}
__device__ __forceinline__ uint32_t smem_u32(const void* p) {
    return (uint32_t)__cvta_generic_to_shared(p);
}
__device__ __forceinline__ void ldm4(uint32_t* r, uint32_t addr) {
    asm volatile("ldmatrix.sync.aligned.m8n8.x4.shared.b16 {%0,%1,%2,%3}, [%4];"
                 : "=r"(r[0]), "=r"(r[1]), "=r"(r[2]), "=r"(r[3]) : "r"(addr));
}
__device__ __forceinline__ void ldm4t(uint32_t* r, uint32_t addr) {
    asm volatile("ldmatrix.sync.aligned.m8n8.x4.trans.shared.b16 {%0,%1,%2,%3}, [%4];"
                 : "=r"(r[0]), "=r"(r[1]), "=r"(r[2]), "=r"(r[3]) : "r"(addr));
}
__device__ __forceinline__ void mma_f16(float* d, const uint32_t* a, const uint32_t* b) {
    asm volatile(
        "mma.sync.aligned.m16n8k16.row.col.f32.f16.f16.f32 "
        "{%0,%1,%2,%3}, {%4,%5,%6,%7}, {%8,%9}, {%0,%1,%2,%3};\n"
        : "+f"(d[0]), "+f"(d[1]), "+f"(d[2]), "+f"(d[3])
        : "r"(a[0]), "r"(a[1]), "r"(a[2]), "r"(a[3]), "r"(b[0]), "r"(b[1]));
}

// ---------------------------------------------------------------------------
// Pre-round weights + inputs to fp16 once.
// ---------------------------------------------------------------------------
struct WPtrs { const float* p[NWMAT]; };

__global__ void w2h_kernel(WPtrs wp, __half* __restrict__ dst) {
    int m = blockIdx.y;
    int i = blockIdx.x * blockDim.x + threadIdx.x;
    dst[m * WELEM + i] = __float2half_rn(wp.p[m][i]);
}
__global__ void a2h_kernel(const float* __restrict__ a, const float* __restrict__ b,
                           __half* __restrict__ oa, __half* __restrict__ ob) {
    int i = blockIdx.x * blockDim.x + threadIdx.x;
    oa[i] = __float2half_rn(a[i]);
    ob[i] = __float2half_rn(b[i]);
}

// ---------------------------------------------------------------------------
// conv1x1 as fp16 tensor-core GEMM: Y[m,n] = sum_k W[m,k] X[k,n] per batch.
// BM=128 (per blockIdx.y; total M = 128*gridDim.y, segmented output across
// consecutive NEL-sized buffers via seg = row>>8), BN=256, BK=32.
// 256 threads, 8 warps 2m x 4n, warp tile 64x64, mma m16n8k16, ldmatrix.
// A smem: [128][40] halves (80B stride, conflict-free for ldmatrix).
// B smem: [32][256] halves, 16B chunks XOR-swizzled j^=(k&7).
// ---------------------------------------------------------------------------
#define CA_BYTES (128 * 80)            // 10240
#define CB_BYTES (32 * 512)            // 16384
#define CSTG     (CA_BYTES + CB_BYTES) // 26624
#define CSMEM    (2 * CSTG)            // 53248

template<bool RELU, bool BIAS, bool OUTF32, bool OUTF16>
__global__ __launch_bounds__(256, 1)
void conv_h_kernel(const __half* __restrict__ X,
                   const __half* __restrict__ Wm,
                   const float* __restrict__ bias,
                   float* __restrict__ Yf,
                   __half* __restrict__ Yh)
{
    extern __shared__ char smem[];

    const int tb_n = blockIdx.x * 256;
    const int tb_m = blockIdx.y * 128;      // row into stacked weight matrix
    const int b    = tb_n >> 12;
    const int p0   = tb_n & 4095;

    const int t    = threadIdx.x;
    const int lane = t & 31;
    const int warp = t >> 5;
    const int wm0  = (warp >> 2) * 64;
    const int wn0  = (warp & 3) * 64;

    const __half* Xbase = X + ((size_t)(b * Cv) << 12) + p0;

    float acc[4][8][4];
    #pragma unroll
    for (int i = 0; i < 4; i++)
        #pragma unroll
        for (int j = 0; j < 8; j++)
            #pragma unroll
            for (int r = 0; r < 4; r++) acc[i][j][r] = 0.0f;

    auto fill = [&](int kt, int s) {
        char* A  = smem + s * CSTG;
        char* Bm = A + CA_BYTES;
        int k0 = kt * 32;
        #pragma unroll
        for (int i = 0; i < 2; i++) {        // A: 512 16B chunks
            int id = t + i * 256;
            int m = id >> 2, q = id & 3;
            cp_async16(A + m * 80 + q * 16,
                       Wm + (size_t)(tb_m + m) * Cv + k0 + q * 8);
        }
        #pragma unroll
        for (int i = 0; i < 4; i++) {        // B: 1024 16B chunks
            int id = t + i * 256;
            int k = id >> 5, j = id & 31;
            cp_async16(Bm + k * 512 + ((j ^ (k & 7)) * 16),
                       Xbase + ((size_t)(k0 + k) << 12) + j * 8);
        }
        cp_commit();
    };

    fill(0, 0);

    const int g_  = lane >> 3;               // ldmatrix tile index
    const int li  = lane & 7;
    const int a_r = lane >> 2;
    const int a_c = lane & 3;

    int buf = 0;
    for (int kt = 0; kt < 8; kt++) {
        cp_wait<0>();
        __syncthreads();
        if (kt + 1 < 8) fill(kt + 1, buf ^ 1);

        uint32_t Ab = smem_u32(smem + buf * CSTG);
        uint32_t Bb = Ab + CA_BYTES;

        #pragma unroll
        for (int ks = 0; ks < 2; ks++) {
            uint32_t afr[4][4], bfr[8][2];
            #pragma unroll
            for (int mi = 0; mi < 4; mi++) {
                int row = wm0 + mi * 16 + (g_ & 1) * 8 + li;
                int ch  = ks * 2 + (g_ >> 1);
                ldm4(afr[mi], Ab + (uint32_t)(row * 80 + ch * 16));
            }
            #pragma unroll
            for (int p = 0; p < 4; p++) {
                int kr = ks * 16 + (g_ & 1) * 8 + li;
                int j  = (wn0 >> 3) + p * 2 + (g_ >> 1);
                uint32_t r4[4];
                ldm4t(r4, Bb + (uint32_t)(kr * 512 + ((j ^ (kr & 7)) * 16)));
                bfr[2 * p][0]     = r4[0];
                bfr[2 * p][1]     = r4[1];
                bfr[2 * p + 1][0] = r4[2];
                bfr[2 * p + 1][1] = r4[3];
            }
            #pragma unroll
            for (int mi = 0; mi < 4; mi++)
                #pragma unroll
                for (int ni = 0; ni < 8; ni++)
                    mma_f16(acc[mi][ni], afr[mi], bfr[ni]);
        }
        __syncthreads();
        buf ^= 1;
    }

    // Epilogue. Row r of stacked M maps to segment r>>8, channel r&255.
    #pragma unroll
    for (int mi = 0; mi < 4; mi++) {
        int rg  = tb_m + wm0 + mi * 16 + a_r;
        int seg = rg >> 8;
        int ch  = rg & 255;
        float bv0 = BIAS ? bias[ch]     : 0.0f;
        float bv1 = BIAS ? bias[ch + 8] : 0.0f;
        #pragma unroll
        for (int ni = 0; ni < 8; ni++) {
            int cb = p0 + wn0 + ni * 8 + 2 * a_c;
            size_t off0 = (size_t)seg * NEL + ((size_t)(b * Cv + ch) << 12) + cb;
            size_t off1 = off0 + ((size_t)8 << 12);

            float v0 = acc[mi][ni][0] + bv0;
            float v1 = acc[mi][ni][1] + bv0;
            float v2 = acc[mi][ni][2] + bv1;
            float v3 = acc[mi][ni][3] + bv1;
            if (RELU) {
                v0 = fmaxf(v0, 0.0f); v1 = fmaxf(v1, 0.0f);
                v2 = fmaxf(v2, 0.0f); v3 = fmaxf(v3, 0.0f);
            }
            if (OUTF32) {
                *(float2*)(Yf + off0) = make_float2(v0, v1);
                *(float2*)(Yf + off1) = make_float2(v2, v3);
            }
            if (OUTF16) {
                *(__half2*)(Yh + off0) = __floats2half2_rn(v0, v1);
                *(__half2*)(Yh + off1) = __floats2half2_rn(v2, v3);
            }
        }
    }
}

// ---------------------------------------------------------------------------
// Fused fc conv + residual + LayerNorm, fp16 MMA.
// BM=256 (all channels), BN=128, BK=32, warp tile 64x64 (4m x 2n).
// A smem [256][40] halves; B smem [32][128] halves swizzled.
// ---------------------------------------------------------------------------
#define LA_BYTES (256 * 80)            // 20480
#define LB_BYTES (32 * 256)            // 8192
#define LSTG     (LA_BYTES + LB_BYTES) // 28672
#define S_STR    257
#define LSMEM    (128 * S_STR * 4)     // 131584 >= 2*LSTG

__global__ __launch_bounds__(256, 1)
void convln_kernel(const __half* __restrict__ X,
                   const __half* __restrict__ Wm,
                   const float* __restrict__ res,
                   const float* __restrict__ g,
                   const float* __restrict__ bt,
                   float* __restrict__ Yf,
                   __half* __restrict__ Yh)
{
    extern __shared__ char smemc[];
    float* smem = (float*)smemc;
    __shared__ float red[2][2][128];
    __shared__ float mus[128], rss[128];

    const int tb_n = blockIdx.x * 128;
    const int b    = tb_n >> 12;
    const int p0   = tb_n & 4095;

    const int t    = threadIdx.x;
    const int lane = t & 31;
    const int warp = t >> 5;
    const int wm0  = (warp >> 1) * 64;
    const int wn0  = (warp & 1) * 64;

    const __half* Xbase = X + ((size_t)(b * Cv) << 12) + p0;

    float acc[4][8][4];
    #pragma unroll
    for (int i = 0; i < 4; i++)
        #pragma unroll
        for (int j = 0; j < 8; j++)
            #pragma unroll
            for (int r = 0; r < 4; r++) acc[i][j][r] = 0.0f;

    auto fill = [&](int kt, int s) {
        char* A  = smemc + s * LSTG;
        char* Bm = A + LA_BYTES;
        int k0 = kt * 32;
        #pragma unroll
        for (int i = 0; i < 4; i++) {        // A: 1024 chunks (256 rows x 4)
            int id = t + i * 256;
            int m = id >> 2, q = id & 3;
            cp_async16(A + m * 80 + q * 16,
                       Wm + (size_t)m * Cv + k0 + q * 8);
        }
        #pragma unroll
        for (int i = 0; i < 2; i++) {        // B: 512 chunks (32 rows x 16)
            int id = t + i * 256;
            int k = id >> 4, j = id & 15;
            cp_async16(Bm + k * 256 + ((j ^ (k & 7)) * 16),
                       Xbase + ((size_t)(k0 + k) << 12) + j * 8);
        }
        cp_commit();
    };

    fill(0, 0);

    const int g_  = lane >> 3;
    const int li  = lane & 7;
    const int a_r = lane >> 2;
    const int a_c = lane & 3;

    int buf = 0;
    for (int kt = 0; kt < 8; kt++) {
        cp_wait<0>();
        __syncthreads();
        if (kt + 1 < 8) fill(kt + 1, buf ^ 1);

        uint32_t Ab = smem_u32(smemc + buf * LSTG);
        uint32_t Bb = Ab + LA_BYTES;

        #pragma unroll
        for (int ks = 0; ks < 2; ks++) {
            uint32_t afr[4][4], bfr[8][2];
            #pragma unroll
            for (int mi = 0; mi < 4; mi++) {
                int row = wm0 + mi * 16 + (g_ & 1) * 8 + li;
                int ch  = ks * 2 + (g_ >> 1);
                ldm4(afr[mi], Ab + (uint32_t)(row * 80 + ch * 16));
            }
            #pragma unroll
            for (int p = 0; p < 4; p++) {
                int kr = ks * 16 + (g_ & 1) * 8 + li;
                int j  = (wn0 >> 3) + p * 2 + (g_ >> 1);
                uint32_t r4[4];
                ldm4t(r4, Bb + (uint32_t)(kr * 256 + ((j ^ (kr & 7)) * 16)));
                bfr[2 * p][0]     = r4[0];
                bfr[2 * p][1]     = r4[1];
                bfr[2 * p + 1][0] = r4[2];
                bfr[2 * p + 1][1] = r4[3];
            }
            #pragma unroll
            for (int mi = 0; mi < 4; mi++)
                #pragma unroll
                for (int ni = 0; ni < 8; ni++)
                    mma_f16(acc[mi][ni], afr[mi], bfr[ni]);
        }
        __syncthreads();
        buf ^= 1;
    }

    // Phase 1: fragments + residual -> S[pixel][channel]
    float* S = smem;
    #pragma unroll
    for (int mi = 0; mi < 4; mi++) {
        int rbase = wm0 + mi * 16 + a_r;
        #pragma unroll
        for (int ni = 0; ni < 8; ni++) {
            int cbase = wn0 + ni * 8 + 2 * a_c;
            size_t off0 = ((size_t)(b * Cv + rbase) << 12) + p0 + cbase;
            size_t off1 = off0 + ((size_t)8 << 12);
            float2 r0 = *(const float2*)(res + off0);
            float2 r1 = *(const float2*)(res + off1);
            S[cbase * S_STR + rbase]           = acc[mi][ni][0] + r0.x;
            S[(cbase + 1) * S_STR + rbase]     = acc[mi][ni][1] + r0.y;
            S[cbase * S_STR + rbase + 8]       = acc[mi][ni][2] + r1.x;
            S[(cbase + 1) * S_STR + rbase + 8] = acc[mi][ni][3] + r1.y;
        }
    }
    __syncthreads();

    // Phase 2: per-pixel mean/var.
    {
        int p = t & 127, q = t >> 7;
        float s = 0.0f, s2 = 0.0f;
        const float* row = S + p * S_STR + q * 128;
        #pragma unroll 8
        for (int j = 0; j < 128; j++) { float v = row[j]; s += v; s2 += v * v; }
        red[0][q][p] = s; red[1][q][p] = s2;
    }
    __syncthreads();
    if (t < 128) {
        float s  = red[0][0][t] + red[0][1][t];
        float s2 = red[1][0][t] + red[1][1][t];
        float mu  = s * (1.0f / Cv);
        float var = s2 * (1.0f / Cv) - mu * mu;
        mus[t] = mu;
        rss[t] = rsqrtf(var + 1e-6f);
    }
    __syncthreads();

    // Phase 3: normalize + dual write (fp32 for residual users, fp16 for GEMMs).
    {
        int p = t & 127;
        float mu = mus[p], rstd = rss[p];
        int c0 = t >> 7;
        #pragma unroll 4
        for (int i = 0; i < 128; i++) {
            int c = c0 + 2 * i;
            float v = (S[p * S_STR + c] - mu) * rstd * g[c] + bt[c];
            size_t off = ((size_t)(b * Cv + c) << 12) + p0 + p;
            Yf[off] = v;
            Yh[off] = __float2half_rn(v);
        }
    }
}

// ---------------------------------------------------------------------------
// Local 3x3 windowed attention (split-d, 2 threads per pixel-head).
// Reads fp32 Q/K/V, writes fp16 (feeds fc GEMM).
// ---------------------------------------------------------------------------
__global__ void local_attn2_kernel(const float* __restrict__ Q,
                                   const float* __restrict__ K,
                                   const float* __restrict__ V,
                                   __half* __restrict__ O)
{
    __shared__ float lg[256][11];

    const int t = threadIdx.x;
    const int u = blockIdx.x * 128 + (t & 127);
    const int h = t >> 7;

    int p    = u & 4095;
    int x    = p & 63;
    int y    = p >> 6;
    int head = (u >> 12) & 7;
    int b    = u >> 15;

    size_t chbase = ((size_t)(b * Cv + head * DHEAD + h * 16)) << 12;

    float q[16];
    #pragma unroll
    for (int d = 0; d < 16; d++) q[d] = Q[chbase + ((size_t)d << 12) + p];

    float lgt[9];
    #pragma unroll
    for (int ki = 0; ki < 3; ki++) {
        #pragma unroll
        for (int kj = 0; kj < 3; kj++) {
            int yy = y + ki - 1, xx = x + kj - 1;
            float acc = 0.0f;
            if (yy >= 0 && yy < Hv && xx >= 0 && xx < Wv) {
                int pp = yy * Wv + xx;
                #pragma unroll
                for (int d = 0; d < 16; d++)
                    acc = fmaf(q[d], K[chbase + ((size_t)d << 12) + pp], acc);
            }
            lgt[ki * 3 + kj] = acc;
        }
    }

    #pragma unroll
    for (int j = 0; j < 9; j++) lg[t][j] = lgt[j];
    __syncthreads();

    const float scale = 0.17677669529663687f;
    const int pt = t ^ 128;
    #pragma unroll
    for (int j = 0; j < 9; j++) lgt[j] = (lgt[j] + lg[pt][j]) * scale;

    float m = lgt[0];
    #pragma unroll
    for (int i = 1; i < 9; i++) m = fmaxf(m, lgt[i]);
    float wgt[9]; float s = 0.0f;
    #pragma unroll
    for (int i = 0; i < 9; i++) { wgt[i] = __expf(lgt[i] - m); s += wgt[i]; }
    float inv = 1.0f / s;
    #pragma unroll
    for (int i = 0; i < 9; i++) wgt[i] *= inv;

    #pragma unroll
    for (int d = 0; d < 16; d++) {
        float acc = 0.0f;
        #pragma unroll
        for (int ki = 0; ki < 3; ki++) {
            #pragma unroll
            for (int kj = 0; kj < 3; kj++) {
                int yy = y + ki - 1, xx = x + kj - 1;
                if (yy >= 0 && yy < Hv && xx >= 0 && xx < Wv)
                    acc = fmaf(wgt[ki * 3 + kj],
                               V[chbase + ((size_t)d << 12) + yy * Wv + xx], acc);
            }
        }
        O[chbase + ((size_t)d << 12) + p] = __float2half_rn(acc);
    }
}

// ---------------------------------------------------------------------------
// BatchNorm over (B,H,W) per channel, fused +residual.
// ---------------------------------------------------------------------------
__global__ void batchnorm_kernel(const float* __restrict__ X,
                                 const float* __restrict__ g,
                                 const float* __restrict__ bt,
                                 const float* __restrict__ res,
                                 float* __restrict__ Y)
{
    int c = blockIdx.x;
    __shared__ float ssum[256], ssum2[256];
    float s = 0.0f, s2 = 0.0f;
    for (int b = 0; b < Bv; b++) {
        const float* xp = X + (((size_t)(b * Cv + c)) << 12);
        for (int p = threadIdx.x; p < HW; p += 256) {
            float v = xp[p];
            s += v; s2 += v * v;
        }
    }
    ssum[threadIdx.x] = s; ssum2[threadIdx.x] = s2;
    __syncthreads();
    for (int off = 128; off > 0; off >>= 1) {
        if (threadIdx.x < off) {
            ssum[threadIdx.x]  += ssum[threadIdx.x + off];
            ssum2[threadIdx.x] += ssum2[threadIdx.x + off];
        }
        __syncthreads();
    }
    float mu   = ssum[0] * (1.0f / (Bv * HW));
    float var  = ssum2[0] * (1.0f / (Bv * HW)) - mu * mu;
    float rstd = rsqrtf(var + 1e-5f);
    float gg = g[c], bb = bt[c];
    for (int b = 0; b < Bv; b++) {
        size_t off = ((size_t)(b * Cv + c)) << 12;
        for (int p = threadIdx.x; p < HW; p += 256)
            Y[off + p] = (X[off + p] - mu) * rstd * gg + bb + res[off + p];
    }
}

// ---------------------------------------------------------------------------
// Host-side orchestration
// ---------------------------------------------------------------------------
extern "C" void kernel_launch(void* const* d_in, const int* in_sizes, int n_in,
                              void* d_out, int out_size)
{
    const float* input1 = (const float*)d_in[0];
    const float* input2 = (const float*)d_in[1];
    const float* slf_g  = (const float*)d_in[6];
    const float* slf_b  = (const float*)d_in[7];
    const float* crs_g  = (const float*)d_in[12];
    const float* crs_b  = (const float*)d_in[13];
    const float* ffn_b1 = (const float*)d_in[15];
    const float* ffn_b2 = (const float*)d_in[17];
    const float* bn_g   = (const float*)d_in[18];
    const float* bn_b   = (const float*)d_in[19];

    cudaFuncSetAttribute(conv_h_kernel<false, false, true, false>,
                         cudaFuncAttributeMaxDynamicSharedMemorySize, CSMEM);
    cudaFuncSetAttribute(conv_h_kernel<true, true, false, true>,
                         cudaFuncAttributeMaxDynamicSharedMemorySize, CSMEM);
    cudaFuncSetAttribute(conv_h_kernel<false, true, true, false>,
                         cudaFuncAttributeMaxDynamicSharedMemorySize, CSMEM);
    cudaFuncSetAttribute(convln_kernel,
                         cudaFuncAttributeMaxDynamicSharedMemorySize, LSMEM);

    float* buf = nullptr;
    cudaGetSymbolAddress((void**)&buf, g_scratch);
    float* Qb  = buf + 0u * NEL;
    float* Kb  = buf + 1u * NEL;
    float* Vb  = buf + 2u * NEL;
    float* T1  = buf + 3u * NEL;   // slf1 fp32
    float* T2  = buf + 4u * NEL;   // slf2 fp32
    float* C1  = buf + 5u * NEL;   // crs1 fp32
    float* C2  = buf + 6u * NEL;   // crs2 fp32
    float* Tmp = buf + 7u * NEL;   // ffn conv2 out fp32

    __half* Hb   = (__half*)(buf + 8u * NEL);
    __half* in1h = Hb + 0u * NEL;
    __half* in2h = Hb + 1u * NEL;
    __half* Obh  = Hb + 2u * NEL;  // attn out fp16
    __half* T1h  = Hb + 3u * NEL;
    __half* T2h  = Hb + 4u * NEL;
    __half* C1h  = Hb + 5u * NEL;
    __half* C2h  = Hb + 6u * NEL;
    __half* Hhh  = Hb + 7u * NEL;  // ffn hidden fp16
    __half* Wh   = Hb + 8u * NEL;  // fp16 weights (10 matrices)

    WPtrs wp;
    wp.p[0] = (const float*)d_in[2];  wp.p[1] = (const float*)d_in[3];
    wp.p[2] = (const float*)d_in[4];  wp.p[3] = (const float*)d_in[5];
    wp.p[4] = (const float*)d_in[8];  wp.p[5] = (const float*)d_in[9];
    wp.p[6] = (const float*)d_in[10]; wp.p[7] = (const float*)d_in[11];
    wp.p[8] = (const float*)d_in[14]; wp.p[9] = (const float*)d_in[16];
    w2h_kernel<<<dim3(WELEM / 1024, NWMAT), 1024>>>(wp, Wh);
    a2h_kernel<<<NEL / 1024, 1024>>>(input1, input2, in1h, in2h);

    float* out1 = (float*)d_out;
    float* out2 = out1 + NEL;
    dim3 bb(256);

    // ---- slf1: fused QKV (slf wq,wk,wv contiguous, M=768) ----
    conv_h_kernel<false, false, true, false><<<dim3(64, 6), bb, CSMEM>>>(
        in1h, Wh, nullptr, Qb, nullptr);
    local_attn2_kernel<<<1024, 256>>>(Qb, Kb, Vb, Obh);
    convln_kernel<<<128, bb, LSMEM>>>(Obh, Wh + 3u * WELEM, input1,
                                      slf_g, slf_b, T1, T1h);
    // ---- slf2 ----
    conv_h_kernel<false, false, true, false><<<dim3(64, 6), bb, CSMEM>>>(
        in2h, Wh, nullptr, Qb, nullptr);
    local_attn2_kernel<<<1024, 256>>>(Qb, Kb, Vb, Obh);
    convln_kernel<<<128, bb, LSMEM>>>(Obh, Wh + 3u * WELEM, input2,
                                      slf_g, slf_b, T2, T2h);
    // ---- crs1: Q from slf1, fused KV (crs wk,wv contiguous) from slf2 ----
    conv_h_kernel<false, false, true, false><<<dim3(64, 2), bb, CSMEM>>>(
        T1h, Wh + 4u * WELEM, nullptr, Qb, nullptr);
    conv_h_kernel<false, false, true, false><<<dim3(64, 4), bb, CSMEM>>>(
        T2h, Wh + 5u * WELEM, nullptr, Kb, nullptr);
    local_attn2_kernel<<<1024, 256>>>(Qb, Kb, Vb, Obh);
    convln_kernel<<<128, bb, LSMEM>>>(Obh, Wh + 7u * WELEM, T1,
                                      crs_g, crs_b, C1, C1h);
    // ---- crs2: Q from slf2, KV from slf1 ----
    conv_h_kernel<false, false, true, false><<<dim3(64, 2), bb, CSMEM>>>(
        T2h, Wh + 4u * WELEM, nullptr, Qb, nullptr);
    conv_h_kernel<false, false, true, false><<<dim3(64, 4), bb, CSMEM>>>(
        T1h, Wh + 5u * WELEM, nullptr, Kb, nullptr);
    local_attn2_kernel<<<1024, 256>>>(Qb, Kb, Vb, Obh);
    convln_kernel<<<128, bb, LSMEM>>>(Obh, Wh + 7u * WELEM, T2,
                                      crs_g, crs_b, C2, C2h);
    // ---- ffn1 ----
    conv_h_kernel<true, true, false, true><<<dim3(64, 2), bb, CSMEM>>>(
        C1h, Wh + 8u * WELEM, ffn_b1, nullptr, Hhh);
    conv_h_kernel<false, true, true, false><<<dim3(64, 2), bb, CSMEM>>>(
        Hhh, Wh + 9u * WELEM, ffn_b2, Tmp, nullptr);
    batchnorm_kernel<<<Cv, 256>>>(Tmp, bn_g, bn_b, C1, out1);
    // ---- ffn2 ----
    conv_h_kernel<true, true, false, true><<<dim3(64, 2), bb, CSMEM>>>(
        C2h, Wh + 8u * WELEM, ffn_b1, nullptr, Hhh);
    conv_h_kernel<false, true, true, false><<<dim3(64, 2), bb, CSMEM>>>(
        Hhh, Wh + 9u * WELEM, ffn_b2, Tmp, nullptr);
    batchnorm_kernel<<<Cv, 256>>>(Tmp, bn_g, bn_b, C2, out2);
}

// round 10
// speedup vs baseline: 1.2845x; 1.2845x over previous
#include <cuda_runtime.h>
#include <cuda_bf16.h>
#include <cstdint>
#include <math.h>

// Problem constants
#define Bv   4
#define Cv   256
#define Hv   64
#define Wv   64
#define HW   4096          // Hv*Wv
#define NPIX 16384         // Bv*HW
#define NEL  4194304u      // Bv*Cv*HW
#define NHEAD 8
#define DHEAD 32
#define WELEM 65536        // 256*256 weight matrix elems
#define NWMAT 10

// Scratch: 16 fp32 tensors + pre-rounded weights (~271 MB).
__device__ float g_scratch[16u * NEL + NWMAT * WELEM];

// ---------------------------------------------------------------------------
// PTX helpers
// ---------------------------------------------------------------------------
__device__ __forceinline__ void cp_async16(void* smem_dst, const void* gsrc) {
    uint32_t s = (uint32_t)__cvta_generic_to_shared(smem_dst);
    asm volatile("cp.async.ca.shared.global [%0], [%1], 16;\n" :: "r"(s), "l"(gsrc));
}
__device__ __forceinline__ void cp_commit() {
    asm volatile("cp.async.commit_group;\n");
}
__device__ __forceinline__ void cp_wait0() {
    asm volatile("cp.async.wait_group 0;\n");
}
__device__ __forceinline__ uint32_t f2tf32(float x) {
    uint32_t y;
    asm("cvt.rna.tf32.f32 %0, %1;" : "=r"(y) : "f"(x));
    return y;
}
__device__ __forceinline__ void mma_tf32(float* d, const uint32_t* a, const uint32_t* b) {
    asm volatile(
        "mma.sync.aligned.m16n8k8.row.col.f32.tf32.tf32.f32 "
        "{%0,%1,%2,%3}, {%4,%5,%6,%7}, {%8,%9}, {%0,%1,%2,%3};\n"
        : "+f"(d[0]), "+f"(d[1]), "+f"(d[2]), "+f"(d[3])
        : "r"(a[0]), "r"(a[1]), "r"(a[2]), "r"(a[3]), "r"(b[0]), "r"(b[1]));
}

// ---------------------------------------------------------------------------
// Pre-round 10 weight matrices to tf32 (RNA) once.
// ---------------------------------------------------------------------------
struct WPtrs { const float* p[NWMAT]; };

__global__ void round_weights_kernel(WPtrs wp, float* __restrict__ dst) {
    int m = blockIdx.y;
    int i = blockIdx.x * blockDim.x + threadIdx.x;
    dst[m * WELEM + i] = __uint_as_float(f2tf32(wp.p[m][i]));
}

// ---------------------------------------------------------------------------
// conv1x1 as tf32 tensor-core GEMM, z-batched over two chains.
// Y[m,n] = sum_k W[m,k] X[k,n] per batch; W pre-rounded tf32 (raw-bit A).
// Stacked-M: blockIdx.y spans M=128 rows of a stacked weight block; output
// row rg maps to segment rg>>8 (consecutive NEL-sized buffers) channel rg&255.
// BM=128, BN=256, BK=32, 256 threads, 8 warps 2m x 4n, warp tile 64x64.
// ---------------------------------------------------------------------------
#define BK     32
#define A_STR  36
#define B_STR  264
#define A_SZ   (128 * A_STR)
#define B_SZ   (BK * B_STR)
#define STG    (A_SZ + B_SZ)
#define SMEM_BYTES (2 * STG * 4)       // 104448 B

template<bool RELU, bool BIAS>
__global__ __launch_bounds__(256, 1)
void conv1x1_tc_kernel(const float* __restrict__ X0, const float* __restrict__ X1,
                       const float* __restrict__ Wm,
                       const float* __restrict__ bias,
                       float* __restrict__ Y0, float* __restrict__ Y1)
{
    extern __shared__ float smem[];

    const float* X = blockIdx.z ? X1 : X0;
    float*       Y = blockIdx.z ? Y1 : Y0;

    const int tb_n = blockIdx.x * 256;     // pixel-block
    const int tb_m = blockIdx.y * 128;     // stacked weight row block
    const int b    = tb_n >> 12;
    const int p0   = tb_n & 4095;

    const int t    = threadIdx.x;
    const int lane = t & 31;
    const int warp = t >> 5;
    const int wm0  = (warp >> 2) * 64;
    const int wn0  = (warp & 3) * 64;

    const float* Xbase = X + ((size_t)(b * Cv) << 12) + p0;

    float acc[4][8][4];
    #pragma unroll
    for (int i = 0; i < 4; i++)
        #pragma unroll
        for (int j = 0; j < 8; j++)
            #pragma unroll
            for (int r = 0; r < 4; r++) acc[i][j][r] = 0.0f;

    auto load_tile = [&](int kt, int s) {
        float* As = smem + s * STG;
        float* Bs = As + A_SZ;
        int k0 = kt * BK;
        #pragma unroll
        for (int i = 0; i < 4; i++) {
            int id = t + i * 256;
            int m  = id >> 3;
            int kq = id & 7;
            cp_async16(&As[m * A_STR + kq * 4],
                       Wm + (size_t)(tb_m + m) * Cv + k0 + kq * 4);
        }
        #pragma unroll
        for (int i = 0; i < 8; i++) {
            int id = t + i * 256;
            int kk = id >> 6;
            int nq = id & 63;
            cp_async16(&Bs[kk * B_STR + nq * 4],
                       Xbase + ((size_t)(k0 + kk) << 12) + nq * 4);
        }
        cp_commit();
    };

    load_tile(0, 0);

    const int a_r = lane >> 2;
    const int a_c = lane & 3;

    int buf = 0;
    const int KT = Cv / BK;
    for (int kt = 0; kt < KT; kt++) {
        cp_wait0();
        __syncthreads();
        if (kt + 1 < KT) load_tile(kt + 1, buf ^ 1);

        const float* As = smem + buf * STG;
        const float* Bs = As + A_SZ;

        #pragma unroll
        for (int ks = 0; ks < 4; ks++) {
            int kb = ks * 8;
            uint32_t afr[4][4], bfr[8][2];
            #pragma unroll
            for (int mi = 0; mi < 4; mi++) {
                const float* ap = As + (wm0 + mi * 16 + a_r) * A_STR + kb + a_c;
                afr[mi][0] = __float_as_uint(ap[0]);
                afr[mi][1] = __float_as_uint(ap[8 * A_STR]);
                afr[mi][2] = __float_as_uint(ap[4]);
                afr[mi][3] = __float_as_uint(ap[8 * A_STR + 4]);
            }
            #pragma unroll
            for (int ni = 0; ni < 8; ni++) {
                const float* bp = Bs + (kb + a_c) * B_STR + wn0 + ni * 8 + a_r;
                bfr[ni][0] = f2tf32(bp[0]);
                bfr[ni][1] = f2tf32(bp[4 * B_STR]);
            }
            #pragma unroll
            for (int mi = 0; mi < 4; mi++)
                #pragma unroll
                for (int ni = 0; ni < 8; ni++)
                    mma_tf32(acc[mi][ni], afr[mi], bfr[ni]);
        }
        __syncthreads();
        buf ^= 1;
    }

    #pragma unroll
    for (int mi = 0; mi < 4; mi++) {
        int rg  = tb_m + wm0 + mi * 16 + a_r;
        int seg = rg >> 8;
        int ch  = rg & 255;
        float bv0 = BIAS ? bias[ch]     : 0.0f;
        float bv1 = BIAS ? bias[ch + 8] : 0.0f;
        float* Ys = Y + (size_t)seg * NEL;
        #pragma unroll
        for (int ni = 0; ni < 8; ni++) {
            int cb = p0 + wn0 + ni * 8 + 2 * a_c;
            size_t off0 = ((size_t)(b * Cv + ch) << 12) + cb;
            size_t off1 = off0 + ((size_t)8 << 12);

            float v0 = acc[mi][ni][0] + bv0;
            float v1 = acc[mi][ni][1] + bv0;
            float v2 = acc[mi][ni][2] + bv1;
            float v3 = acc[mi][ni][3] + bv1;
            if (RELU) {
                v0 = fmaxf(v0, 0.0f); v1 = fmaxf(v1, 0.0f);
                v2 = fmaxf(v2, 0.0f); v3 = fmaxf(v3, 0.0f);
            }
            *(float2*)(Ys + off0) = make_float2(v0, v1);
            *(float2*)(Ys + off1) = make_float2(v2, v3);
        }
    }
}

// ---------------------------------------------------------------------------
// Fused fc conv + residual + LayerNorm, z-batched.
// BM=256 (all channels), BN=128, BK=32, warp tile 64x64 (4m x 2n).
// ---------------------------------------------------------------------------
#define LA_STR 36
#define LB_STR 136
#define LA_SZ  (256 * LA_STR)
#define LB_SZ  (32 * LB_STR)
#define LSTG   (LA_SZ + LB_SZ)
#define S_STR  257
#define LSMEM_BYTES (128 * S_STR * 4)  // 131584 >= 2*LSTG*4

__global__ __launch_bounds__(256, 1)
void convln_kernel(const float* __restrict__ X0, const float* __restrict__ X1,
                   const float* __restrict__ Wm,
                   const float* __restrict__ res0, const float* __restrict__ res1,
                   const float* __restrict__ g,
                   const float* __restrict__ bt,
                   float* __restrict__ Y0, float* __restrict__ Y1)
{
    extern __shared__ float smem[];
    __shared__ float red[2][2][128];
    __shared__ float mus[128], rss[128];

    const float* X   = blockIdx.y ? X1   : X0;
    const float* res = blockIdx.y ? res1 : res0;
    float*       Y   = blockIdx.y ? Y1   : Y0;

    const int tb_n = blockIdx.x * 128;
    const int b    = tb_n >> 12;
    const int p0   = tb_n & 4095;

    const int t    = threadIdx.x;
    const int lane = t & 31;
    const int warp = t >> 5;
    const int wm0  = (warp >> 1) * 64;
    const int wn0  = (warp & 1) * 64;

    const float* Xbase = X + ((size_t)(b * Cv) << 12) + p0;

    float acc[4][8][4];
    #pragma unroll
    for (int i = 0; i < 4; i++)
        #pragma unroll
        for (int j = 0; j < 8; j++)
            #pragma unroll
            for (int r = 0; r < 4; r++) acc[i][j][r] = 0.0f;

    auto load_tile = [&](int kt, int s) {
        float* As = smem + s * LSTG;
        float* Bs = As + LA_SZ;
        int k0 = kt * BK;
        #pragma unroll
        for (int i = 0; i < 8; i++) {
            int id = t + i * 256;
            int m  = id >> 3;
            int kq = id & 7;
            cp_async16(&As[m * LA_STR + kq * 4],
                       Wm + (size_t)m * Cv + k0 + kq * 4);
        }
        #pragma unroll
        for (int i = 0; i < 4; i++) {
            int id = t + i * 256;
            int kk = id >> 5;
            int nq = id & 31;
            cp_async16(&Bs[kk * LB_STR + nq * 4],
                       Xbase + ((size_t)(k0 + kk) << 12) + nq * 4);
        }
        cp_commit();
    };

    load_tile(0, 0);

    const int a_r = lane >> 2;
    const int a_c = lane & 3;

    int buf = 0;
    const int KT = Cv / BK;
    for (int kt = 0; kt < KT; kt++) {
        cp_wait0();
        __syncthreads();
        if (kt + 1 < KT) load_tile(kt + 1, buf ^ 1);

        const float* As = smem + buf * LSTG;
        const float* Bs = As + LA_SZ;

        #pragma unroll
        for (int ks = 0; ks < 4; ks++) {
            int kb = ks * 8;
            uint32_t afr[4][4], bfr[8][2];
            #pragma unroll
            for (int mi = 0; mi < 4; mi++) {
                const float* ap = As + (wm0 + mi * 16 + a_r) * LA_STR + kb + a_c;
                afr[mi][0] = __float_as_uint(ap[0]);
                afr[mi][1] = __float_as_uint(ap[8 * LA_STR]);
                afr[mi][2] = __float_as_uint(ap[4]);
                afr[mi][3] = __float_as_uint(ap[8 * LA_STR + 4]);
            }
            #pragma unroll
            for (int ni = 0; ni < 8; ni++) {
                const float* bp = Bs + (kb + a_c) * LB_STR + wn0 + ni * 8 + a_r;
                bfr[ni][0] = f2tf32(bp[0]);
                bfr[ni][1] = f2tf32(bp[4 * LB_STR]);
            }
            #pragma unroll
            for (int mi = 0; mi < 4; mi++)
                #pragma unroll
                for (int ni = 0; ni < 8; ni++)
                    mma_tf32(acc[mi][ni], afr[mi], bfr[ni]);
        }
        __syncthreads();
        buf ^= 1;
    }

    // Phase 1: fragments + residual -> S[pixel][channel]
    float* S = smem;
    #pragma unroll
    for (int mi = 0; mi < 4; mi++) {
        int rbase = wm0 + mi * 16 + a_r;
        #pragma unroll
        for (int ni = 0; ni < 8; ni++) {
            int cbase = wn0 + ni * 8 + 2 * a_c;
            size_t off0 = ((size_t)(b * Cv + rbase) << 12) + p0 + cbase;
            size_t off1 = off0 + ((size_t)8 << 12);
            float2 r0 = *(const float2*)(res + off0);
            float2 r1 = *(const float2*)(res + off1);
            S[cbase * S_STR + rbase]           = acc[mi][ni][0] + r0.x;
            S[(cbase + 1) * S_STR + rbase]     = acc[mi][ni][1] + r0.y;
            S[cbase * S_STR + rbase + 8]       = acc[mi][ni][2] + r1.x;
            S[(cbase + 1) * S_STR + rbase + 8] = acc[mi][ni][3] + r1.y;
        }
    }
    __syncthreads();

    // Phase 2: per-pixel mean/var.
    {
        int p = t & 127, q = t >> 7;
        float s = 0.0f, s2 = 0.0f;
        const float* row = S + p * S_STR + q * 128;
        #pragma unroll 8
        for (int j = 0; j < 128; j++) { float v = row[j]; s += v; s2 += v * v; }
        red[0][q][p] = s; red[1][q][p] = s2;
    }
    __syncthreads();
    if (t < 128) {
        float s  = red[0][0][t] + red[0][1][t];
        float s2 = red[1][0][t] + red[1][1][t];
        float mu  = s * (1.0f / Cv);
        float var = s2 * (1.0f / Cv) - mu * mu;
        mus[t] = mu;
        rss[t] = rsqrtf(var + 1e-6f);
    }
    __syncthreads();

    // Phase 3: normalize + write.
    {
        int p = t & 127;
        float mu = mus[p], rstd = rss[p];
        int c0 = t >> 7;
        #pragma unroll 4
        for (int i = 0; i < 128; i++) {
            int c = c0 + 2 * i;
            float v = S[p * S_STR + c];
            Y[((size_t)(b * Cv + c) << 12) + p0 + p] =
                (v - mu) * rstd * g[c] + bt[c];
        }
    }
}

// ---------------------------------------------------------------------------
// Local 3x3 windowed attention, one thread per (b, head, pixel), z-batched.
// (R3-proven layout: 28.5us per chain.)
// ---------------------------------------------------------------------------
__global__ void local_attn_kernel(const float* __restrict__ Q0, const float* __restrict__ K0,
                                  const float* __restrict__ V0, float* __restrict__ O0,
                                  const float* __restrict__ Q1, const float* __restrict__ K1,
                                  const float* __restrict__ V1, float* __restrict__ O1)
{
    const float* Q = blockIdx.y ? Q1 : Q0;
    const float* K = blockIdx.y ? K1 : K0;
    const float* V = blockIdx.y ? V1 : V0;
    float*       O = blockIdx.y ? O1 : O0;

    int n = blockIdx.x * blockDim.x + threadIdx.x;   // 0 .. 131071
    int p    = n & 4095;
    int x    = p & 63;
    int y    = p >> 6;
    int head = (n >> 12) & 7;
    int b    = n >> 15;

    size_t chbase = ((size_t)(b * Cv + head * DHEAD)) << 12;

    float q[DHEAD];
    #pragma unroll
    for (int d = 0; d < DHEAD; d++) q[d] = Q[chbase + ((size_t)d << 12) + p];

    const float scale = 0.17677669529663687f; // 1/sqrt(32)

    float logits[9];
    #pragma unroll
    for (int ki = 0; ki < 3; ki++) {
        #pragma unroll
        for (int kj = 0; kj < 3; kj++) {
            int yy = y + ki - 1, xx = x + kj - 1;
            float acc = 0.0f;
            if (yy >= 0 && yy < Hv && xx >= 0 && xx < Wv) {
                int pp = yy * Wv + xx;
                #pragma unroll
                for (int d = 0; d < DHEAD; d++)
                    acc = fmaf(q[d], K[chbase + ((size_t)d << 12) + pp], acc);
                acc *= scale;
            }
            logits[ki * 3 + kj] = acc;
        }
    }

    float m = logits[0];
    #pragma unroll
    for (int i = 1; i < 9; i++) m = fmaxf(m, logits[i]);
    float wgt[9]; float s = 0.0f;
    #pragma unroll
    for (int i = 0; i < 9; i++) { wgt[i] = __expf(logits[i] - m); s += wgt[i]; }
    float inv = 1.0f / s;
    #pragma unroll
    for (int i = 0; i < 9; i++) wgt[i] *= inv;

    #pragma unroll
    for (int d = 0; d < DHEAD; d++) {
        float acc = 0.0f;
        #pragma unroll
        for (int ki = 0; ki < 3; ki++) {
            #pragma unroll
            for (int kj = 0; kj < 3; kj++) {
                int yy = y + ki - 1, xx = x + kj - 1;
                if (yy >= 0 && yy < Hv && xx >= 0 && xx < Wv)
                    acc = fmaf(wgt[ki * 3 + kj],
                               V[chbase + ((size_t)d << 12) + yy * Wv + xx], acc);
            }
        }
        O[chbase + ((size_t)d << 12) + p] = acc;
    }
}

// ---------------------------------------------------------------------------
// BatchNorm over (B,H,W) per channel, fused +residual, z-batched.
// ---------------------------------------------------------------------------
__global__ void batchnorm_kernel(const float* __restrict__ X0, const float* __restrict__ X1,
                                 const float* __restrict__ g,
                                 const float* __restrict__ bt,
                                 const float* __restrict__ res0, const float* __restrict__ res1,
                                 float* __restrict__ Y0, float* __restrict__ Y1)
{
    const float* X   = blockIdx.y ? X1   : X0;
    const float* res = blockIdx.y ? res1 : res0;
    float*       Y   = blockIdx.y ? Y1   : Y0;

    int c = blockIdx.x;
    __shared__ float ssum[256], ssum2[256];
    float s = 0.0f, s2 = 0.0f;
    for (int b = 0; b < Bv; b++) {
        const float* xp = X + (((size_t)(b * Cv + c)) << 12);
        for (int p = threadIdx.x; p < HW; p += 256) {
            float v = xp[p];
            s += v; s2 += v * v;
        }
    }
    ssum[threadIdx.x] = s; ssum2[threadIdx.x] = s2;
    __syncthreads();
    for (int off = 128; off > 0; off >>= 1) {
        if (threadIdx.x < off) {
            ssum[threadIdx.x]  += ssum[threadIdx.x + off];
            ssum2[threadIdx.x] += ssum2[threadIdx.x + off];
        }
        __syncthreads();
    }
    float mu   = ssum[0] * (1.0f / (Bv * HW));
    float var  = ssum2[0] * (1.0f / (Bv * HW)) - mu * mu;
    float rstd = rsqrtf(var + 1e-5f);
    float gg = g[c], bb = bt[c];
    for (int b = 0; b < Bv; b++) {
        size_t off = ((size_t)(b * Cv + c)) << 12;
        for (int p = threadIdx.x; p < HW; p += 256)
            Y[off + p] = (X[off + p] - mu) * rstd * gg + bb + res[off + p];
    }
}

// ---------------------------------------------------------------------------
// Host-side orchestration
// ---------------------------------------------------------------------------
extern "C" void kernel_launch(void* const* d_in, const int* in_sizes, int n_in,
                              void* d_out, int out_size)
{
    const float* input1 = (const float*)d_in[0];
    const float* input2 = (const float*)d_in[1];
    const float* slf_g  = (const float*)d_in[6];
    const float* slf_b  = (const float*)d_in[7];
    const float* crs_g  = (const float*)d_in[12];
    const float* crs_b  = (const float*)d_in[13];
    const float* ffn_b1 = (const float*)d_in[15];
    const float* ffn_b2 = (const float*)d_in[17];
    const float* bn_g   = (const float*)d_in[18];
    const float* bn_b   = (const float*)d_in[19];

    cudaFuncSetAttribute(conv1x1_tc_kernel<false, false>,
                         cudaFuncAttributeMaxDynamicSharedMemorySize, SMEM_BYTES);
    cudaFuncSetAttribute(conv1x1_tc_kernel<true, true>,
                         cudaFuncAttributeMaxDynamicSharedMemorySize, SMEM_BYTES);
    cudaFuncSetAttribute(conv1x1_tc_kernel<false, true>,
                         cudaFuncAttributeMaxDynamicSharedMemorySize, SMEM_BYTES);
    cudaFuncSetAttribute(convln_kernel,
                         cudaFuncAttributeMaxDynamicSharedMemorySize, LSMEM_BYTES);

    float* buf = nullptr;
    cudaGetSymbolAddress((void**)&buf, g_scratch);
    float* Q1   = buf + 0u * NEL;   // Q1,K1,V1 consecutive (QKV segments)
    float* K1   = buf + 1u * NEL;
    float* V1   = buf + 2u * NEL;
    float* Q2   = buf + 3u * NEL;   // Q2,K2,V2 consecutive
    float* K2   = buf + 4u * NEL;
    float* V2   = buf + 5u * NEL;
    float* Ob1  = buf + 6u * NEL;
    float* Ob2  = buf + 7u * NEL;
    float* T1   = buf + 8u * NEL;
    float* T2   = buf + 9u * NEL;
    float* C1   = buf + 10u * NEL;
    float* C2   = buf + 11u * NEL;
    float* H1   = buf + 12u * NEL;
    float* H2   = buf + 13u * NEL;
    float* Tm1  = buf + 14u * NEL;
    float* Tm2  = buf + 15u * NEL;
    float* W8   = buf + 16u * NEL;  // pre-rounded weights

    WPtrs wp;
    wp.p[0] = (const float*)d_in[2];  // slf_wq
    wp.p[1] = (const float*)d_in[3];  // slf_wk
    wp.p[2] = (const float*)d_in[4];  // slf_wv
    wp.p[3] = (const float*)d_in[5];  // slf_fc
    wp.p[4] = (const float*)d_in[8];  // crs_wq
    wp.p[5] = (const float*)d_in[9];  // crs_wk
    wp.p[6] = (const float*)d_in[10]; // crs_wv
    wp.p[7] = (const float*)d_in[11]; // crs_fc
    wp.p[8] = (const float*)d_in[14]; // ffn_w1
    wp.p[9] = (const float*)d_in[16]; // ffn_w2
    round_weights_kernel<<<dim3(WELEM / 1024, NWMAT), 1024>>>(wp, W8);

    float* out1 = (float*)d_out;
    float* out2 = out1 + NEL;
    dim3 bb(256);

    // ---- slf phase (both chains in one z=2 launch per stage) ----
    // QKV: stacked slf wq|wk|wv (rows 0..767) -> segments Q,K,V.
    conv1x1_tc_kernel<false, false><<<dim3(64, 6, 2), bb, SMEM_BYTES>>>(
        input1, input2, W8, nullptr, Q1, Q2);
    local_attn_kernel<<<dim3(512, 2), bb>>>(Q1, K1, V1, Ob1, Q2, K2, V2, Ob2);
    convln_kernel<<<dim3(128, 2), bb, LSMEM_BYTES>>>(
        Ob1, Ob2, W8 + 3u * WELEM, input1, input2, slf_g, slf_b, T1, T2);

    // ---- crs phase ----
    // Q: crs_wq on (T1 | T2).
    conv1x1_tc_kernel<false, false><<<dim3(64, 2, 2), bb, SMEM_BYTES>>>(
        T1, T2, W8 + 4u * WELEM, nullptr, Q1, Q2);
    // KV: stacked crs wk|wv (rows 0..511) on swapped inputs (T2 | T1).
    conv1x1_tc_kernel<false, false><<<dim3(64, 4, 2), bb, SMEM_BYTES>>>(
        T2, T1, W8 + 5u * WELEM, nullptr, K1, K2);
    local_attn_kernel<<<dim3(512, 2), bb>>>(Q1, K1, V1, Ob1, Q2, K2, V2, Ob2);
    convln_kernel<<<dim3(128, 2), bb, LSMEM_BYTES>>>(
        Ob1, Ob2, W8 + 7u * WELEM, T1, T2, crs_g, crs_b, C1, C2);

    // ---- ffn phase ----
    conv1x1_tc_kernel<true, true><<<dim3(64, 2, 2), bb, SMEM_BYTES>>>(
        C1, C2, W8 + 8u * WELEM, ffn_b1, H1, H2);
    conv1x1_tc_kernel<false, true><<<dim3(64, 2, 2), bb, SMEM_BYTES>>>(
        H1, H2, W8 + 9u * WELEM, ffn_b2, Tm1, Tm2);
    batchnorm_kernel<<<dim3(Cv, 2), bb>>>(
        Tm1, Tm2, bn_g, bn_b, C1, C2, out1, out2);
}